// round 15
// baseline (speedup 1.0000x reference)
#include <cuda_runtime.h>
#include <cuda_fp16.h>
#include <math.h>
#include <stdint.h>

// Problem dims (fixed)
#define T_DIM   512
#define B_DIM   64
#define IN_DIM  512
#define H_DIM   1024
#define OUT_DIM 512
#define M_DIM   (T_DIM * B_DIM)   // 32768
#define G3H     (3 * H_DIM)       // 3072

// ---------------------------------------------------------------------------
// Static device scratch
//  A-side (activations): fp16 hi + fp16 lo   (full fp32 precision recovered)
//  B-side (weights):     fp16 only           (dropped term ~2^-12)
// ---------------------------------------------------------------------------
__device__ float  g_G [(size_t)M_DIM * G3H];      // post-act gates fp32
__device__ __half g_xh[(size_t)M_DIM * IN_DIM];
__device__ __half g_xl[(size_t)M_DIM * IN_DIM];
__device__ __half g_Hh[(size_t)M_DIM * H_DIM];
__device__ __half g_Hl[(size_t)M_DIM * H_DIM];
__device__ __half g_W0h[IN_DIM * G3H];
__device__ __half g_W1h[H_DIM * G3H];
__device__ __half g_Wfh[H_DIM * OUT_DIM];

// ---------------------------------------------------------------------------
// PTX helpers
// ---------------------------------------------------------------------------
__device__ __forceinline__ uint32_t smem_u32(const void* p) {
    return (uint32_t)__cvta_generic_to_shared(p);
}
__device__ __forceinline__ void cp_async16(uint32_t saddr, const void* g) {
    asm volatile("cp.async.cg.shared.global [%0], [%1], 16;\n" :: "r"(saddr), "l"(g));
}
__device__ __forceinline__ void cp_commit() {
    asm volatile("cp.async.commit_group;\n");
}
template<int N> __device__ __forceinline__ void cp_wait() {
    asm volatile("cp.async.wait_group %0;\n" :: "n"(N));
}
__device__ __forceinline__ void ldmx4(uint32_t* r, uint32_t addr) {
    asm volatile("ldmatrix.sync.aligned.m8n8.x4.shared.b16 {%0,%1,%2,%3}, [%4];\n"
                 : "=r"(r[0]), "=r"(r[1]), "=r"(r[2]), "=r"(r[3]) : "r"(addr));
}
__device__ __forceinline__ void ldmx4t(uint32_t* r, uint32_t addr) {
    asm volatile("ldmatrix.sync.aligned.m8n8.x4.trans.shared.b16 {%0,%1,%2,%3}, [%4];\n"
                 : "=r"(r[0]), "=r"(r[1]), "=r"(r[2]), "=r"(r[3]) : "r"(addr));
}
__device__ __forceinline__ void mma16816h(float* d, const uint32_t* a,
                                          uint32_t b0, uint32_t b1) {
    asm volatile(
        "mma.sync.aligned.m16n8k16.row.col.f32.f16.f16.f32 "
        "{%0,%1,%2,%3}, {%4,%5,%6,%7}, {%8,%9}, {%0,%1,%2,%3};\n"
        : "+f"(d[0]), "+f"(d[1]), "+f"(d[2]), "+f"(d[3])
        : "r"(a[0]), "r"(a[1]), "r"(a[2]), "r"(a[3]), "r"(b0), "r"(b1));
}

// ---------------------------------------------------------------------------
// fp16x2 split GEMM with fused bias + activation epilogue (R13 structure —
// best measured: hi chain then lo chain, RAW reuse distance 16 issues).
//   C = act( Ah@Bh + Al@Bh + bias )      (= A@Bh exactly, B fp16-truncated)
// 128x128x64 CTA tile, 8 warps (4M x 2N), 2-stage double buffer, 2 CTAs/SM.
// actMode: 0 none (FC); 1 gates (cols < H_DIM tanh, else sigmoid).
// ---------------------------------------------------------------------------
#define STAGE_BYTES 49152     // [Ah 16K][Al 16K][Bh 16K]
#define NSTAGE 2
#define GEMM_SMEM (NSTAGE * STAGE_BYTES)

__global__ __launch_bounds__(256, 2)
void gemm2_f16_kernel(int M, int N, int K,
                      const __half* __restrict__ Ah,
                      const __half* __restrict__ Al,
                      const __half* __restrict__ Bh,
                      const float* __restrict__ bias,
                      float* __restrict__ C,
                      int actMode)
{
    extern __shared__ char smem[];
    const uint32_t sbase = smem_u32(smem);

    const int tid    = threadIdx.x;
    const int lane   = tid & 31;
    const int warpId = tid >> 5;
    const int warpM  = warpId & 3;
    const int warpN  = warpId >> 2;

    const int rowBase = blockIdx.y * 128;
    const int colBase = blockIdx.x * 128;

    float acc[2][8][4];
    #pragma unroll
    for (int g = 0; g < 2; g++)
        #pragma unroll
        for (int n = 0; n < 8; n++)
            #pragma unroll
            for (int q = 0; q < 4; q++) acc[g][n][q] = 0.f;

    // stage: A tiles 128 rows x 128B (8 chunks/row, SW128), B 64 rows x 256B
    auto load_stage = [&](int s, int k0) {
        const uint32_t st = sbase + s * STAGE_BYTES;
        #pragma unroll
        for (int i = 0; i < 4; i++) {
            const int ch  = tid + i * 256;
            const int row = ch >> 3;
            const int c   = ch & 7;
            const uint32_t soff = row * 128 + ((c ^ (row & 7)) << 4);
            const size_t goff = (size_t)(rowBase + row) * K + k0 + c * 8;
            cp_async16(st + soff,         Ah + goff);
            cp_async16(st + 16384 + soff, Al + goff);
        }
        #pragma unroll
        for (int i = 0; i < 4; i++) {
            const int ch  = tid + i * 256;
            const int row = ch >> 4;
            const int c   = ch & 15;
            const uint32_t soff = row * 256 + ((c ^ (row & 7)) << 4);
            const size_t goff = (size_t)(k0 + row) * N + colBase + c * 8;
            cp_async16(st + 32768 + soff, Bh + goff);
        }
        cp_commit();
    };

    auto compute_stage = [&](int s) {
        const uint32_t aH = sbase + s * STAGE_BYTES;
        const uint32_t aL = aH + 16384;
        const uint32_t bH = aH + 32768;

        #pragma unroll
        for (int ks = 0; ks < 4; ks++) {
            uint32_t ah[2][4], al[2][4];
            #pragma unroll
            for (int g = 0; g < 2; g++) {
                const int row = warpM * 32 + g * 16 + (lane & 15);
                const int cb  = ks * 2 + (lane >> 4);      // 0..7
                const int sc  = cb ^ (row & 7);
                const uint32_t off = row * 128 + sc * 16;
                ldmx4(ah[g], aH + off);
                ldmx4(al[g], aL + off);
            }
            uint32_t bh[4][4];
            #pragma unroll
            for (int j = 0; j < 4; j++) {
                const int row = ks * 16 + (lane & 15);
                const int cb  = warpN * 8 + j * 2 + (lane >> 4);
                const int sc  = cb ^ (row & 7);
                ldmx4t(bh[j], bH + row * 256 + sc * 16);
            }
            // hi chain: 16 MMAs, all distinct accumulators
            #pragma unroll
            for (int j = 0; j < 4; j++)
                #pragma unroll
                for (int g = 0; g < 2; g++) {
                    mma16816h(acc[g][2*j],   ah[g], bh[j][0], bh[j][1]);
                    mma16816h(acc[g][2*j+1], ah[g], bh[j][2], bh[j][3]);
                }
            // lo chain: 16 MMAs, each 16 issues after its RAW producer
            #pragma unroll
            for (int j = 0; j < 4; j++)
                #pragma unroll
                for (int g = 0; g < 2; g++) {
                    mma16816h(acc[g][2*j],   al[g], bh[j][0], bh[j][1]);
                    mma16816h(acc[g][2*j+1], al[g], bh[j][2], bh[j][3]);
                }
        }
    };

    const int KT = K >> 6;   // K/64: 8 or 16
    load_stage(0, 0);
    for (int kt = 0; kt < KT; kt++) {
        cp_wait<0>();
        __syncthreads();
        if (kt + 1 < KT) load_stage((kt + 1) & 1, (kt + 1) * 64);
        compute_stage(kt & 1);
    }

    // ---- fused epilogue: +bias, activation, store ----
    const int doTanh = (actMode == 1) && (colBase < H_DIM);
    const int doSig  = (actMode == 1) && (colBase >= H_DIM);

    #pragma unroll
    for (int g = 0; g < 2; g++) {
        const int r0 = rowBase + warpM * 32 + g * 16 + (lane >> 2);
        #pragma unroll
        for (int n = 0; n < 8; n++) {
            const int col = colBase + warpN * 64 + n * 8 + (lane & 3) * 2;
            const float b0 = __ldg(bias + col);
            const float b1 = __ldg(bias + col + 1);
            float v[4] = { acc[g][n][0] + b0, acc[g][n][1] + b1,
                           acc[g][n][2] + b0, acc[g][n][3] + b1 };
            if (doTanh) {
                #pragma unroll
                for (int q = 0; q < 4; q++)
                    v[q] = 1.0f - __fdividef(2.0f, __expf(2.0f * v[q]) + 1.0f);
            } else if (doSig) {
                #pragma unroll
                for (int q = 0; q < 4; q++)
                    v[q] = __fdividef(1.0f, 1.0f + __expf(-v[q]));
            }
            *(float2*)(C + (size_t)r0 * N + col)       = make_float2(v[0], v[1]);
            *(float2*)(C + (size_t)(r0 + 8) * N + col) = make_float2(v[2], v[3]);
        }
    }
}

// ---------------------------------------------------------------------------
// Fused prep: x -> (xh, xl) split; W0/W1/Wfc -> fp16. One launch, float4 I/O.
// Region sizes in float4 units (compile-time).
// ---------------------------------------------------------------------------
#define NX4   (M_DIM * IN_DIM / 4)               // 4,194,304
#define NW04  (IN_DIM * G3H / 4)                 //   393,216
#define NW14  (H_DIM * G3H / 4)                  //   786,432
#define NWF4  (H_DIM * OUT_DIM / 4)              //   131,072
#define NTOT4 (NX4 + NW04 + NW14 + NWF4)         // 5,505,024

union H4 { __half h[4]; uint2 u; };

__device__ __forceinline__ void cvt4(const float4 v, __half* dst, int i4) {
    H4 o;
    o.h[0] = __float2half(v.x); o.h[1] = __float2half(v.y);
    o.h[2] = __float2half(v.z); o.h[3] = __float2half(v.w);
    *(uint2*)(dst + (size_t)i4 * 4) = o.u;
}

__global__ void prep_kernel(const float* __restrict__ x,
                            const float* __restrict__ W0,
                            const float* __restrict__ W1,
                            const float* __restrict__ Wfc,
                            __half* __restrict__ xh, __half* __restrict__ xl,
                            __half* __restrict__ W0h,
                            __half* __restrict__ W1h,
                            __half* __restrict__ Wfh)
{
    int i = blockIdx.x * blockDim.x + threadIdx.x;
    if (i < NX4) {
        float4 v = ((const float4*)x)[i];
        H4 hh, ll;
        float vv[4] = {v.x, v.y, v.z, v.w};
        #pragma unroll
        for (int j = 0; j < 4; j++) {
            __half h = __float2half(vv[j]);
            hh.h[j] = h;
            ll.h[j] = __float2half(vv[j] - __half2float(h));
        }
        *(uint2*)(xh + (size_t)i * 4) = hh.u;
        *(uint2*)(xl + (size_t)i * 4) = ll.u;
    } else if (i < NX4 + NW04) {
        const int j = i - NX4;
        cvt4(((const float4*)W0)[j], W0h, j);
    } else if (i < NX4 + NW04 + NW14) {
        const int j = i - NX4 - NW04;
        cvt4(((const float4*)W1)[j], W1h, j);
    } else if (i < NTOT4) {
        const int j = i - NX4 - NW04 - NW14;
        cvt4(((const float4*)Wfc)[j], Wfh, j);
    }
}

// ---------------------------------------------------------------------------
// fo-pool scan, 2 h-lanes per thread (float2 / half2 vectorized).
// G holds post-act gates: z'=tanh(z), f'=sigmoid(f), o'=sigmoid(o)
//   c = fma(f', c - z', z') ;  v = o'*c -> fp16 hi/lo
// Per-element arithmetic identical to scalar version (bit-identical output).
// ---------------------------------------------------------------------------
__global__ void qrnn_scan_kernel(const float* __restrict__ G,
                                 __half* __restrict__ Hh,
                                 __half* __restrict__ Hl)
{
    const int idx = blockIdx.x * blockDim.x + threadIdx.x;
    if (idx >= B_DIM * (H_DIM / 2)) return;
    const int b  = idx / (H_DIM / 2);
    const int hp = (idx % (H_DIM / 2)) * 2;

    float c0 = 0.0f, c1 = 0.0f;
    #pragma unroll 4
    for (int t = 0; t < T_DIM; t++) {
        const size_t base = ((size_t)t * B_DIM + b) * G3H + hp;
        const float2 z = *(const float2*)(G + base);
        const float2 f = *(const float2*)(G + base + H_DIM);
        const float2 o = *(const float2*)(G + base + 2 * H_DIM);
        c0 = fmaf(f.x, c0 - z.x, z.x);
        c1 = fmaf(f.y, c1 - z.y, z.y);
        const float v0 = o.x * c0;
        const float v1 = o.y * c1;
        const __half h0 = __float2half(v0);
        const __half h1 = __float2half(v1);
        const size_t oidx = ((size_t)t * B_DIM + b) * H_DIM + hp;
        __half2 hi; hi.x = h0; hi.y = h1;
        __half2 lo;
        lo.x = __float2half(v0 - __half2float(h0));
        lo.y = __float2half(v1 - __half2float(h1));
        *(__half2*)(Hh + oidx) = hi;
        *(__half2*)(Hl + oidx) = lo;
    }
}

// ---------------------------------------------------------------------------
// Launch: prep -> gemm0 -> scan0 -> gemm1 -> scan1 -> fc   (6 launches)
// ---------------------------------------------------------------------------
extern "C" void kernel_launch(void* const* d_in, const int* in_sizes, int n_in,
                              void* d_out, int out_size)
{
    const float* x   = (const float*)d_in[0];
    const float* W0  = (const float*)d_in[1];
    const float* b0  = (const float*)d_in[2];
    const float* W1  = (const float*)d_in[3];
    const float* b1  = (const float*)d_in[4];
    const float* Wfc = (const float*)d_in[5];
    const float* bfc = (const float*)d_in[6];
    float* out = (float*)d_out;

    float* G;
    __half *xh, *xl, *Hh, *Hl, *W0h, *W1h, *Wfh;
    cudaGetSymbolAddress((void**)&G,   g_G);
    cudaGetSymbolAddress((void**)&xh,  g_xh);
    cudaGetSymbolAddress((void**)&xl,  g_xl);
    cudaGetSymbolAddress((void**)&Hh,  g_Hh);
    cudaGetSymbolAddress((void**)&Hl,  g_Hl);
    cudaGetSymbolAddress((void**)&W0h, g_W0h);
    cudaGetSymbolAddress((void**)&W1h, g_W1h);
    cudaGetSymbolAddress((void**)&Wfh, g_Wfh);

    static bool attr_done = false;
    if (!attr_done) {
        cudaFuncSetAttribute(gemm2_f16_kernel,
                             cudaFuncAttributeMaxDynamicSharedMemorySize,
                             GEMM_SMEM);
        attr_done = true;
    }

    dim3 blk(256);
    dim3 grid_g(G3H / 128, M_DIM / 128);      // 24 x 256
    dim3 grid_fc(OUT_DIM / 128, M_DIM / 128); // 4 x 256
    dim3 grid_scan((B_DIM * (H_DIM / 2) + 255) / 256);   // 128 blocks
    dim3 grid_prep((NTOT4 + 255) / 256);                 // 21504 blocks

    // 1: fused splits / conversions
    prep_kernel<<<grid_prep, blk>>>(x, W0, W1, Wfc, xh, xl, W0h, W1h, Wfh);

    // 2-3: layer 0
    gemm2_f16_kernel<<<grid_g, blk, GEMM_SMEM>>>(M_DIM, G3H, IN_DIM,
                                                 xh, xl, W0h, b0, G, 1);
    qrnn_scan_kernel<<<grid_scan, blk>>>(G, Hh, Hl);

    // 4-5: layer 1
    gemm2_f16_kernel<<<grid_g, blk, GEMM_SMEM>>>(M_DIM, G3H, H_DIM,
                                                 Hh, Hl, W1h, b1, G, 1);
    qrnn_scan_kernel<<<grid_scan, blk>>>(G, Hh, Hl);

    // 6: FC head (no act)
    gemm2_f16_kernel<<<grid_fc, blk, GEMM_SMEM>>>(M_DIM, OUT_DIM, H_DIM,
                                                  Hh, Hl, Wfh, bfc, out, 0);
}

// round 17
// speedup vs baseline: 1.0672x; 1.0672x over previous
#include <cuda_runtime.h>
#include <cuda_fp16.h>
#include <math.h>
#include <stdint.h>

// Problem dims (fixed)
#define T_DIM   512
#define B_DIM   64
#define IN_DIM  512
#define H_DIM   1024
#define OUT_DIM 512
#define M_DIM   (T_DIM * B_DIM)   // 32768
#define G3H     (3 * H_DIM)       // 3072

// ---------------------------------------------------------------------------
// Static device scratch
//  A-side (activations): fp16 hi + fp16 lo   (full fp32 precision recovered)
//  B-side (weights):     fp16 only           (dropped term ~2^-12)
// ---------------------------------------------------------------------------
__device__ float  g_G [(size_t)M_DIM * G3H];      // post-act gates fp32
__device__ __half g_xh[(size_t)M_DIM * IN_DIM];
__device__ __half g_xl[(size_t)M_DIM * IN_DIM];
__device__ __half g_Hh[(size_t)M_DIM * H_DIM];
__device__ __half g_Hl[(size_t)M_DIM * H_DIM];
__device__ __half g_W0h[IN_DIM * G3H];
__device__ __half g_W1h[H_DIM * G3H];
__device__ __half g_Wfh[H_DIM * OUT_DIM];

// ---------------------------------------------------------------------------
// PTX helpers
// ---------------------------------------------------------------------------
__device__ __forceinline__ uint32_t smem_u32(const void* p) {
    return (uint32_t)__cvta_generic_to_shared(p);
}
__device__ __forceinline__ void cp_async16(uint32_t saddr, const void* g) {
    asm volatile("cp.async.cg.shared.global [%0], [%1], 16;\n" :: "r"(saddr), "l"(g));
}
__device__ __forceinline__ void cp_commit() {
    asm volatile("cp.async.commit_group;\n");
}
template<int N> __device__ __forceinline__ void cp_wait() {
    asm volatile("cp.async.wait_group %0;\n" :: "n"(N));
}
__device__ __forceinline__ void ldmx4(uint32_t* r, uint32_t addr) {
    asm volatile("ldmatrix.sync.aligned.m8n8.x4.shared.b16 {%0,%1,%2,%3}, [%4];\n"
                 : "=r"(r[0]), "=r"(r[1]), "=r"(r[2]), "=r"(r[3]) : "r"(addr));
}
__device__ __forceinline__ void ldmx4t(uint32_t* r, uint32_t addr) {
    asm volatile("ldmatrix.sync.aligned.m8n8.x4.trans.shared.b16 {%0,%1,%2,%3}, [%4];\n"
                 : "=r"(r[0]), "=r"(r[1]), "=r"(r[2]), "=r"(r[3]) : "r"(addr));
}
__device__ __forceinline__ void mma16816h(float* d, const uint32_t* a,
                                          uint32_t b0, uint32_t b1) {
    asm volatile(
        "mma.sync.aligned.m16n8k16.row.col.f32.f16.f16.f32 "
        "{%0,%1,%2,%3}, {%4,%5,%6,%7}, {%8,%9}, {%0,%1,%2,%3};\n"
        : "+f"(d[0]), "+f"(d[1]), "+f"(d[2]), "+f"(d[3])
        : "r"(a[0]), "r"(a[1]), "r"(a[2]), "r"(a[3]), "r"(b0), "r"(b1));
}

// ---------------------------------------------------------------------------
// fp16x2 split GEMM with fused bias + activation epilogue (R13 structure —
// best measured: hi chain then lo chain, RAW reuse distance 16 issues).
//   C = act( Ah@Bh + Al@Bh + bias )      (= A@Bh exactly, B fp16-truncated)
// 128x128x64 CTA tile, 8 warps (4M x 2N), 2-stage double buffer, 2 CTAs/SM.
// actMode: 0 none (FC); 1 gates (cols < H_DIM tanh, else sigmoid).
// ---------------------------------------------------------------------------
#define STAGE_BYTES 49152     // [Ah 16K][Al 16K][Bh 16K]
#define NSTAGE 2
#define GEMM_SMEM (NSTAGE * STAGE_BYTES)

__global__ __launch_bounds__(256, 2)
void gemm2_f16_kernel(int M, int N, int K,
                      const __half* __restrict__ Ah,
                      const __half* __restrict__ Al,
                      const __half* __restrict__ Bh,
                      const float* __restrict__ bias,
                      float* __restrict__ C,
                      int actMode)
{
    extern __shared__ char smem[];
    const uint32_t sbase = smem_u32(smem);

    const int tid    = threadIdx.x;
    const int lane   = tid & 31;
    const int warpId = tid >> 5;
    const int warpM  = warpId & 3;
    const int warpN  = warpId >> 2;

    const int rowBase = blockIdx.y * 128;
    const int colBase = blockIdx.x * 128;

    float acc[2][8][4];
    #pragma unroll
    for (int g = 0; g < 2; g++)
        #pragma unroll
        for (int n = 0; n < 8; n++)
            #pragma unroll
            for (int q = 0; q < 4; q++) acc[g][n][q] = 0.f;

    // stage: A tiles 128 rows x 128B (8 chunks/row, SW128), B 64 rows x 256B
    auto load_stage = [&](int s, int k0) {
        const uint32_t st = sbase + s * STAGE_BYTES;
        #pragma unroll
        for (int i = 0; i < 4; i++) {
            const int ch  = tid + i * 256;
            const int row = ch >> 3;
            const int c   = ch & 7;
            const uint32_t soff = row * 128 + ((c ^ (row & 7)) << 4);
            const size_t goff = (size_t)(rowBase + row) * K + k0 + c * 8;
            cp_async16(st + soff,         Ah + goff);
            cp_async16(st + 16384 + soff, Al + goff);
        }
        #pragma unroll
        for (int i = 0; i < 4; i++) {
            const int ch  = tid + i * 256;
            const int row = ch >> 4;
            const int c   = ch & 15;
            const uint32_t soff = row * 256 + ((c ^ (row & 7)) << 4);
            const size_t goff = (size_t)(k0 + row) * N + colBase + c * 8;
            cp_async16(st + 32768 + soff, Bh + goff);
        }
        cp_commit();
    };

    auto compute_stage = [&](int s) {
        const uint32_t aH = sbase + s * STAGE_BYTES;
        const uint32_t aL = aH + 16384;
        const uint32_t bH = aH + 32768;

        #pragma unroll
        for (int ks = 0; ks < 4; ks++) {
            uint32_t ah[2][4], al[2][4];
            #pragma unroll
            for (int g = 0; g < 2; g++) {
                const int row = warpM * 32 + g * 16 + (lane & 15);
                const int cb  = ks * 2 + (lane >> 4);      // 0..7
                const int sc  = cb ^ (row & 7);
                const uint32_t off = row * 128 + sc * 16;
                ldmx4(ah[g], aH + off);
                ldmx4(al[g], aL + off);
            }
            uint32_t bh[4][4];
            #pragma unroll
            for (int j = 0; j < 4; j++) {
                const int row = ks * 16 + (lane & 15);
                const int cb  = warpN * 8 + j * 2 + (lane >> 4);
                const int sc  = cb ^ (row & 7);
                ldmx4t(bh[j], bH + row * 256 + sc * 16);
            }
            // hi chain: 16 MMAs, all distinct accumulators
            #pragma unroll
            for (int j = 0; j < 4; j++)
                #pragma unroll
                for (int g = 0; g < 2; g++) {
                    mma16816h(acc[g][2*j],   ah[g], bh[j][0], bh[j][1]);
                    mma16816h(acc[g][2*j+1], ah[g], bh[j][2], bh[j][3]);
                }
            // lo chain: 16 MMAs, each 16 issues after its RAW producer
            #pragma unroll
            for (int j = 0; j < 4; j++)
                #pragma unroll
                for (int g = 0; g < 2; g++) {
                    mma16816h(acc[g][2*j],   al[g], bh[j][0], bh[j][1]);
                    mma16816h(acc[g][2*j+1], al[g], bh[j][2], bh[j][3]);
                }
        }
    };

    const int KT = K >> 6;   // K/64: 8 or 16
    load_stage(0, 0);
    for (int kt = 0; kt < KT; kt++) {
        cp_wait<0>();
        __syncthreads();
        if (kt + 1 < KT) load_stage((kt + 1) & 1, (kt + 1) * 64);
        compute_stage(kt & 1);
    }

    // ---- fused epilogue: +bias, activation, store ----
    const int doTanh = (actMode == 1) && (colBase < H_DIM);
    const int doSig  = (actMode == 1) && (colBase >= H_DIM);

    #pragma unroll
    for (int g = 0; g < 2; g++) {
        const int r0 = rowBase + warpM * 32 + g * 16 + (lane >> 2);
        #pragma unroll
        for (int n = 0; n < 8; n++) {
            const int col = colBase + warpN * 64 + n * 8 + (lane & 3) * 2;
            const float b0 = __ldg(bias + col);
            const float b1 = __ldg(bias + col + 1);
            float v[4] = { acc[g][n][0] + b0, acc[g][n][1] + b1,
                           acc[g][n][2] + b0, acc[g][n][3] + b1 };
            if (doTanh) {
                #pragma unroll
                for (int q = 0; q < 4; q++)
                    v[q] = 1.0f - __fdividef(2.0f, __expf(2.0f * v[q]) + 1.0f);
            } else if (doSig) {
                #pragma unroll
                for (int q = 0; q < 4; q++)
                    v[q] = __fdividef(1.0f, 1.0f + __expf(-v[q]));
            }
            *(float2*)(C + (size_t)r0 * N + col)       = make_float2(v[0], v[1]);
            *(float2*)(C + (size_t)(r0 + 8) * N + col) = make_float2(v[2], v[3]);
        }
    }
}

// ---------------------------------------------------------------------------
// Fused prep: x -> (xh, xl) split; W0/W1/Wfc -> fp16. One launch, float4 I/O.
// ---------------------------------------------------------------------------
#define NX4   (M_DIM * IN_DIM / 4)               // 4,194,304
#define NW04  (IN_DIM * G3H / 4)                 //   393,216
#define NW14  (H_DIM * G3H / 4)                  //   786,432
#define NWF4  (H_DIM * OUT_DIM / 4)              //   131,072
#define NTOT4 (NX4 + NW04 + NW14 + NWF4)         // 5,505,024

union H4 { __half h[4]; uint2 u; };

__device__ __forceinline__ void cvt4(const float4 v, __half* dst, int i4) {
    H4 o;
    o.h[0] = __float2half(v.x); o.h[1] = __float2half(v.y);
    o.h[2] = __float2half(v.z); o.h[3] = __float2half(v.w);
    *(uint2*)(dst + (size_t)i4 * 4) = o.u;
}

__global__ void prep_kernel(const float* __restrict__ x,
                            const float* __restrict__ W0,
                            const float* __restrict__ W1,
                            const float* __restrict__ Wfc,
                            __half* __restrict__ xh, __half* __restrict__ xl,
                            __half* __restrict__ W0h,
                            __half* __restrict__ W1h,
                            __half* __restrict__ Wfh)
{
    int i = blockIdx.x * blockDim.x + threadIdx.x;
    if (i < NX4) {
        float4 v = ((const float4*)x)[i];
        H4 hh, ll;
        float vv[4] = {v.x, v.y, v.z, v.w};
        #pragma unroll
        for (int j = 0; j < 4; j++) {
            __half h = __float2half(vv[j]);
            hh.h[j] = h;
            ll.h[j] = __float2half(vv[j] - __half2float(h));
        }
        *(uint2*)(xh + (size_t)i * 4) = hh.u;
        *(uint2*)(xl + (size_t)i * 4) = ll.u;
    } else if (i < NX4 + NW04) {
        const int j = i - NX4;
        cvt4(((const float4*)W0)[j], W0h, j);
    } else if (i < NX4 + NW04 + NW14) {
        const int j = i - NX4 - NW04;
        cvt4(((const float4*)W1)[j], W1h, j);
    } else if (i < NTOT4) {
        const int j = i - NX4 - NW04 - NW14;
        cvt4(((const float4*)Wfc)[j], Wfh, j);
    }
}

// ---------------------------------------------------------------------------
// fo-pool scan (scalar, 1 h-lane/thread — 65536 threads, 256 CTAs; the
// measured-best configuration). G holds post-act gates.
//   c = fma(f', c - z', z') ;  v = o'*c -> fp16 hi/lo
// ---------------------------------------------------------------------------
__global__ void qrnn_scan_kernel(const float* __restrict__ G,
                                 __half* __restrict__ Hh,
                                 __half* __restrict__ Hl)
{
    const int idx = blockIdx.x * blockDim.x + threadIdx.x;
    if (idx >= B_DIM * H_DIM) return;
    const int b = idx / H_DIM;
    const int h = idx % H_DIM;

    float c = 0.0f;
    #pragma unroll 4
    for (int t = 0; t < T_DIM; t++) {
        const size_t base = ((size_t)t * B_DIM + b) * G3H + h;
        const float z = G[base];
        const float f = G[base + H_DIM];
        const float o = G[base + 2 * H_DIM];
        c = fmaf(f, c - z, z);
        const float v = o * c;
        __half hi = __float2half(v);
        const size_t oidx = ((size_t)t * B_DIM + b) * H_DIM + h;
        Hh[oidx] = hi;
        Hl[oidx] = __float2half(v - __half2float(hi));
    }
}

// ---------------------------------------------------------------------------
// Launch: prep -> gemm0 -> scan0 -> gemm1 -> scan1 -> fc   (6 launches)
// ---------------------------------------------------------------------------
extern "C" void kernel_launch(void* const* d_in, const int* in_sizes, int n_in,
                              void* d_out, int out_size)
{
    const float* x   = (const float*)d_in[0];
    const float* W0  = (const float*)d_in[1];
    const float* b0  = (const float*)d_in[2];
    const float* W1  = (const float*)d_in[3];
    const float* b1  = (const float*)d_in[4];
    const float* Wfc = (const float*)d_in[5];
    const float* bfc = (const float*)d_in[6];
    float* out = (float*)d_out;

    float* G;
    __half *xh, *xl, *Hh, *Hl, *W0h, *W1h, *Wfh;
    cudaGetSymbolAddress((void**)&G,   g_G);
    cudaGetSymbolAddress((void**)&xh,  g_xh);
    cudaGetSymbolAddress((void**)&xl,  g_xl);
    cudaGetSymbolAddress((void**)&Hh,  g_Hh);
    cudaGetSymbolAddress((void**)&Hl,  g_Hl);
    cudaGetSymbolAddress((void**)&W0h, g_W0h);
    cudaGetSymbolAddress((void**)&W1h, g_W1h);
    cudaGetSymbolAddress((void**)&Wfh, g_Wfh);

    static bool attr_done = false;
    if (!attr_done) {
        cudaFuncSetAttribute(gemm2_f16_kernel,
                             cudaFuncAttributeMaxDynamicSharedMemorySize,
                             GEMM_SMEM);
        attr_done = true;
    }

    dim3 blk(256);
    dim3 grid_g(G3H / 128, M_DIM / 128);      // 24 x 256
    dim3 grid_fc(OUT_DIM / 128, M_DIM / 128); // 4 x 256
    dim3 grid_scan((B_DIM * H_DIM + 255) / 256);         // 256 blocks
    dim3 grid_prep((NTOT4 + 255) / 256);                 // 21504 blocks

    // 1: fused splits / conversions
    prep_kernel<<<grid_prep, blk>>>(x, W0, W1, Wfc, xh, xl, W0h, W1h, Wfh);

    // 2-3: layer 0
    gemm2_f16_kernel<<<grid_g, blk, GEMM_SMEM>>>(M_DIM, G3H, IN_DIM,
                                                 xh, xl, W0h, b0, G, 1);
    qrnn_scan_kernel<<<grid_scan, blk>>>(G, Hh, Hl);

    // 4-5: layer 1
    gemm2_f16_kernel<<<grid_g, blk, GEMM_SMEM>>>(M_DIM, G3H, H_DIM,
                                                 Hh, Hl, W1h, b1, G, 1);
    qrnn_scan_kernel<<<grid_scan, blk>>>(G, Hh, Hl);

    // 6: FC head (no act)
    gemm2_f16_kernel<<<grid_fc, blk, GEMM_SMEM>>>(M_DIM, OUT_DIM, H_DIM,
                                                  Hh, Hl, Wfh, bfc, out, 0);
}